// round 16
// baseline (speedup 1.0000x reference)
#include <cuda_runtime.h>
#include <cuda_fp16.h>
#include <cstdint>

#define SEQ   2048
#define EMB   1024
#define BATCH 4
#define MTOT  (BATCH * SEQ)   // 8192

// ---------------- scratch (device globals; allocation-free) ----------------
__device__ __half g_xb [(long long)MTOT * EMB];
__device__ __half g_WqT[(long long)EMB * EMB];
__device__ __half g_WkT[(long long)EMB * EMB];
__device__ __half g_WvT[(long long)EMB * EMB];
__device__ __half g_Wo [(long long)EMB * EMB];
__device__ __half g_H  [(long long)EMB * EMB];          // H = Wk^T·Wq
__device__ __half g_G  [(long long)EMB * EMB];          // G = Wo·Wv
__device__ float  g_wu [EMB];
__device__ float  g_wv [EMB];
__device__ float  g_w2 [EMB];
__device__ float  g_c  [1];
__device__ float  g_su [MTOT];
__device__ float  g_sv [MTOT];
__device__ __half g_T  [(long long)MTOT * EMB];         // T = (x·H^T) * (1/32)
__device__ __half g_VWT[(long long)BATCH * EMB * SEQ];
__device__ __half g_Pb [(long long)BATCH * SEQ * SEQ];
__device__ float  g_Spart[(long long)MTOT * 32];

// ---------------- helpers ----------------
__device__ __forceinline__ uint32_t smem_to_u32(const void* p) {
    uint32_t a;
    asm("{ .reg .u64 t; cvta.to.shared.u64 t, %1; cvt.u32.u64 %0, t; }" : "=r"(a) : "l"(p));
    return a;
}

#define CP_ASYNC16(dst, src) \
    asm volatile("cp.async.cg.shared.global [%0], [%1], 16;" :: "r"(dst), "l"(src))
#define CP_COMMIT() asm volatile("cp.async.commit_group;" ::: "memory")

__device__ __forceinline__ void ldmatrix_x4(uint32_t& r0, uint32_t& r1, uint32_t& r2, uint32_t& r3,
                                            uint32_t addr) {
    asm volatile("ldmatrix.sync.aligned.m8n8.x4.shared.b16 {%0,%1,%2,%3}, [%4];"
                 : "=r"(r0), "=r"(r1), "=r"(r2), "=r"(r3) : "r"(addr));
}

__device__ __forceinline__ void mma16816(float* c, uint32_t a0, uint32_t a1, uint32_t a2, uint32_t a3,
                                         uint32_t b0, uint32_t b1) {
    asm volatile("mma.sync.aligned.m16n8k16.row.col.f32.f16.f16.f32 "
                 "{%0,%1,%2,%3}, {%4,%5,%6,%7}, {%8,%9}, {%0,%1,%2,%3};"
                 : "+f"(c[0]), "+f"(c[1]), "+f"(c[2]), "+f"(c[3])
                 : "r"(a0), "r"(a1), "r"(a2), "r"(a3), "r"(b0), "r"(b1));
}

__device__ __forceinline__ uint4 pack8h(const float* v) {
    uint32_t h[4];
    #pragma unroll
    for (int i = 0; i < 4; i++) {
        __half2 hp = __halves2half2(__float2half_rn(v[2 * i]), __float2half_rn(v[2 * i + 1]));
        h[i] = *(uint32_t*)&hp;
    }
    return make_uint4(h[0], h[1], h[2], h[3]);
}

// ---------------- prep: cvt_x + transpose-cvt weights + vec precomputes ----------------
#define PREP_BLOCKS 8233

__global__ __launch_bounds__(256)
void prep_kernel(const float* __restrict__ x,
                 const float* __restrict__ Wq, const float* __restrict__ Wk,
                 const float* __restrict__ Wv, const float* __restrict__ Wo,
                 const float* __restrict__ bq, const float* __restrict__ bk,
                 const float* __restrict__ bv,
                 __half* __restrict__ xb,
                 __half* __restrict__ WqT, __half* __restrict__ WkT,
                 __half* __restrict__ WvT, __half* __restrict__ Woh,
                 float* __restrict__ wu, float* __restrict__ wv,
                 float* __restrict__ w2, float* __restrict__ cc)
{
    int bid = blockIdx.x;
    int tid = threadIdx.x;

    if (bid < 4096) {
        long long idx = ((long long)bid * 256 + tid) * 8;
        const float4* src = (const float4*)(x + idx);
        float v[8];
        float4 f0 = src[0], f1 = src[1];
        v[0]=f0.x; v[1]=f0.y; v[2]=f0.z; v[3]=f0.w;
        v[4]=f1.x; v[5]=f1.y; v[6]=f1.z; v[7]=f1.w;
        *(uint4*)(xb + idx) = pack8h(v);
    } else if (bid < 8192) {
        int t = bid - 4096;
        int w = t >> 10;
        int r0 = ((t >> 5) & 31) * 32;
        int c0 = (t & 31) * 32;
        int tx = tid & 31, ty = tid >> 5;
        const float* src = (w == 0) ? Wq : (w == 1) ? Wk : (w == 2) ? Wv : Wo;
        __half* dst = (w == 0) ? WqT : (w == 1) ? WkT : (w == 2) ? WvT : Woh;
        if (w == 3) {
            #pragma unroll
            for (int k = 0; k < 4; k++) {
                int f = r0 + ty + k * 8;
                dst[(long long)f * EMB + c0 + tx] = __float2half_rn(src[(long long)f * EMB + c0 + tx]);
            }
            return;
        }
        __shared__ __half sm[32][36];
        #pragma unroll
        for (int k = 0; k < 4; k++) {
            int f = r0 + ty + k * 8;
            sm[tx][ty + k * 8] = __float2half_rn(src[(long long)f * EMB + c0 + tx]);
        }
        __syncthreads();
        #pragma unroll
        for (int k = 0; k < 4; k++) {
            int e = c0 + ty + k * 8;
            dst[(long long)e * EMB + r0 + tx] = sm[ty + k * 8][tx];
        }
    } else if (bid < 8200) {
        int y = (bid - 8192) >> 2;
        int e = ((bid - 8192) & 3) * 256 + tid;
        const float* W = (y == 0) ? Wq : Wk;
        const float* b = (y == 0) ? bk : bq;
        float* o = (y == 0) ? wu : wv;
        float s = 0.0f;
        for (int f = 0; f < EMB; f++)
            s += W[(long long)f * EMB + e] * b[f];
        o[e] = s;
    } else if (bid == 8200) {
        __shared__ float red[256];
        float s = 0.0f;
        for (int f = tid; f < EMB; f += 256) s += bq[f] * bk[f];
        red[tid] = s;
        __syncthreads();
        for (int o = 128; o > 0; o >>= 1) {
            if (tid < o) red[tid] += red[tid + o];
            __syncthreads();
        }
        if (tid == 0) cc[0] = red[0];
    } else {
        int f = (bid - 8201) * 32 + (tid >> 3);
        int seg = tid & 7;
        const float* row = Wo + (long long)f * EMB + seg * 128;
        float s = 0.0f;
        #pragma unroll
        for (int g = 0; g < 128; g++) s += row[g] * bv[seg * 128 + g];
        s += __shfl_xor_sync(0xffffffffu, s, 1);
        s += __shfl_xor_sync(0xffffffffu, s, 2);
        s += __shfl_xor_sync(0xffffffffu, s, 4);
        if (seg == 0) w2[f] = s;
    }
}

// ---------------- epilogue writers ----------------
__device__ __forceinline__ void write_h(__half* O, int gm, int gn, int Nl,
                                        float v0, float v1) {
    __half2 hp = __halves2half2(__float2half_rn(v0), __float2half_rn(v1));
    *(__half2*)&O[(long long)gm * Nl + gn] = hp;
}
__device__ __forceinline__ void write_hT(__half* O, int gm, int gn,
                                         float v0, float v1) {
    int b = gm >> 11;
    int sdx = gm & (SEQ - 1);
    long long base = (long long)b * EMB * SEQ + (long long)gn * SEQ + sdx;
    O[base] = __float2half_rn(v0);
    O[base + SEQ] = __float2half_rn(v1);
}

// ---------------- HMMA mainloop (proven core) ----------------
#define BK      64
#define NSTAGE  3
#define STAGE_BYTES 32768
#define GEMM_SMEM (NSTAGE * STAGE_BYTES)

__device__ __forceinline__ void gemm_mainloop(
    const __half* __restrict__ A, const __half* __restrict__ B,
    int m0, int n0, int Ktot, uint32_t smem_base, int tid, int lane,
    int warp_m, int warp_n, float (&acc)[2][8][4])
{
    const int nchunks = Ktot / BK;

    auto load_stage = [&](int chunk, int s) {
        uint32_t sa = smem_base + s * STAGE_BYTES;
        uint32_t sb = sa + 16384;
        long long k0 = (long long)chunk * BK;
        #pragma unroll
        for (int t = 0; t < 4; t++) {
            int idx = tid + t * 256;
            int r = idx >> 3, c = idx & 7;
            uint32_t off = (uint32_t)((r * 8 + (c ^ (r & 7))) * 16);
            CP_ASYNC16(sa + off, (const void*)(A + (long long)(m0 + r) * Ktot + k0 + c * 8));
            CP_ASYNC16(sb + off, (const void*)(B + (long long)(n0 + r) * Ktot + k0 + c * 8));
        }
        CP_COMMIT();
    };

    #pragma unroll
    for (int mi = 0; mi < 2; mi++)
        #pragma unroll
        for (int ni = 0; ni < 8; ni++)
            #pragma unroll
            for (int r = 0; r < 4; r++)
                acc[mi][ni][r] = 0.0f;

    load_stage(0, 0);
    load_stage(1, 1);

    const int a_row = (lane & 15);
    const int a_half = lane >> 4;
    const int b_noff = (lane & 7) + ((lane & 16) ? 8 : 0);
    const int b_kg = (lane & 8) ? 1 : 0;

    for (int i = 0; i < nchunks; i++) {
        if (i + 1 < nchunks) {
            asm volatile("cp.async.wait_group 1;" ::: "memory");
        } else {
            asm volatile("cp.async.wait_group 0;" ::: "memory");
        }
        __syncthreads();

        if (i + 2 < nchunks) load_stage(i + 2, (i + 2) % NSTAGE);

        const int s = i % NSTAGE;
        const uint32_t sa = smem_base + s * STAGE_BYTES;
        const uint32_t sb = sa + 16384;

        #pragma unroll
        for (int kk = 0; kk < 4; kk++) {
            uint32_t af[2][4];
            #pragma unroll
            for (int mi = 0; mi < 2; mi++) {
                int row = warp_m * 32 + mi * 16 + a_row;
                int g = (kk * 2 + a_half) ^ (row & 7);
                ldmatrix_x4(af[mi][0], af[mi][1], af[mi][2], af[mi][3],
                            sa + (uint32_t)((row * 8 + g) * 16));
            }
            uint32_t bf[4][4];
            #pragma unroll
            for (int nt = 0; nt < 4; nt++) {
                int row = warp_n * 64 + nt * 16 + b_noff;
                int g = (kk * 2 + b_kg) ^ (row & 7);
                ldmatrix_x4(bf[nt][0], bf[nt][1], bf[nt][2], bf[nt][3],
                            sb + (uint32_t)((row * 8 + g) * 16));
            }
            #pragma unroll
            for (int mi = 0; mi < 2; mi++)
                #pragma unroll
                for (int ni = 0; ni < 8; ni++) {
                    int nt = ni >> 1;
                    uint32_t bb0 = (ni & 1) ? bf[nt][2] : bf[nt][0];
                    uint32_t bb1 = (ni & 1) ? bf[nt][3] : bf[nt][1];
                    mma16816(acc[mi][ni], af[mi][0], af[mi][1], af[mi][2], af[mi][3], bb0, bb1);
                }
        }
    }
}

// ---- hg + uv merged ----
__global__ __launch_bounds__(256, 2)
void hg_uv(const __half* __restrict__ WkT, const __half* __restrict__ WqT,
           const __half* __restrict__ Wo, const __half* __restrict__ WvT,
           __half* __restrict__ H, __half* __restrict__ G,
           const __half* __restrict__ xb, const float* __restrict__ wu,
           const float* __restrict__ wv, const float* __restrict__ cc,
           float* __restrict__ su, float* __restrict__ sv)
{
    const int tid = threadIdx.x;
    int bid = blockIdx.x;

    if (bid >= 128) {
        const float scale = 1.0f / 32.0f;
        int wid = tid >> 5;
        int lane = tid & 31;
        long long row = (long long)(bid - 128) * 8 + wid;
        const uint4* xr = (const uint4*)(xb + row * EMB);
        float du = 0.0f, dv = 0.0f;
        #pragma unroll
        for (int it = 0; it < 4; it++) {
            int u = it * 32 + lane;
            uint4 q = xr[u];
            const __half2* hp = (const __half2*)&q;
            int e0 = u * 8;
            float4 a0 = *(const float4*)(wu + e0);
            float4 a1 = *(const float4*)(wu + e0 + 4);
            float4 b0 = *(const float4*)(wv + e0);
            float4 b1 = *(const float4*)(wv + e0 + 4);
            float2 x0 = __half22float2(hp[0]);
            float2 x1 = __half22float2(hp[1]);
            float2 x2 = __half22float2(hp[2]);
            float2 x3 = __half22float2(hp[3]);
            du += x0.x*a0.x + x0.y*a0.y + x1.x*a0.z + x1.y*a0.w
                + x2.x*a1.x + x2.y*a1.y + x3.x*a1.z + x3.y*a1.w;
            dv += x0.x*b0.x + x0.y*b0.y + x1.x*b0.z + x1.y*b0.w
                + x2.x*b1.x + x2.y*b1.y + x3.x*b1.z + x3.y*b1.w;
        }
        #pragma unroll
        for (int o = 16; o > 0; o >>= 1) {
            du += __shfl_xor_sync(0xffffffffu, du, o);
            dv += __shfl_xor_sync(0xffffffffu, dv, o);
        }
        if (lane == 0) {
            su[row] = scale * (du + cc[0]);
            sv[row] = scale * dv;
        }
        return;
    }

    extern __shared__ __align__(1024) char smem[];
    const uint32_t smem_base = smem_to_u32(smem);
    const int wid = tid >> 5;
    const int lane = tid & 31;
    const int warp_m = wid & 3;
    const int warp_n = wid >> 2;

    bool isG = (bid >= 64);
    int t = isG ? bid - 64 : bid;
    int m0 = (t >> 3) * 128;
    int n0 = (t & 7) * 128;
    const __half* A = isG ? Wo : WkT;
    const __half* B = isG ? WvT : WqT;
    __half* O = isG ? G : H;

    float acc[2][8][4];
    gemm_mainloop(A, B, m0, n0, EMB, smem_base, tid, lane, warp_m, warp_n, acc);

    const int rbase = m0 + warp_m * 32 + (lane >> 2);
    const int cbase = n0 + warp_n * 64 + (lane & 3) * 2;
    #pragma unroll
    for (int mi = 0; mi < 2; mi++)
        #pragma unroll
        for (int ni = 0; ni < 8; ni++)
            #pragma unroll
            for (int half = 0; half < 2; half++) {
                int gm = rbase + mi * 16 + half * 8;
                int gn = cbase + ni * 8;
                write_h(O, gm, gn, EMB, acc[mi][ni][half * 2 + 0], acc[mi][ni][half * 2 + 1]);
            }
}

// ---- merged: T = (x H^T)/32 (512 tiles) and VW^T (512 tiles) ----
__global__ __launch_bounds__(256, 2)
void tvw_gemm(const __half* __restrict__ xb, const __half* __restrict__ H,
              const __half* __restrict__ G, const float* __restrict__ w2,
              __half* __restrict__ T, __half* __restrict__ VWT)
{
    extern __shared__ __align__(1024) char smem[];
    const uint32_t smem_base = smem_to_u32(smem);
    const int tid = threadIdx.x;
    const int wid = tid >> 5;
    const int lane = tid & 31;
    const int warp_m = wid & 3;
    const int warp_n = wid >> 2;

    int bid = blockIdx.x;
    bool isVW = (bid >= 512);
    int t = isVW ? bid - 512 : bid;
    int m0 = (t >> 3) * 128;
    int n0 = (t & 7) * 128;
    const __half* B = isVW ? G : H;

    float acc[2][8][4];
    gemm_mainloop(xb, B, m0, n0, EMB, smem_base, tid, lane, warp_m, warp_n, acc);

    const float tscale = 1.0f / 32.0f;
    const int rbase = m0 + warp_m * 32 + (lane >> 2);
    const int cbase = n0 + warp_n * 64 + (lane & 3) * 2;
    #pragma unroll
    for (int mi = 0; mi < 2; mi++)
        #pragma unroll
        for (int ni = 0; ni < 8; ni++)
            #pragma unroll
            for (int half = 0; half < 2; half++) {
                int gm = rbase + mi * 16 + half * 8;
                int gn = cbase + ni * 8;
                float v0 = acc[mi][ni][half * 2 + 0];
                float v1 = acc[mi][ni][half * 2 + 1];
                if (isVW) {
                    v0 += w2[gn]; v1 += w2[gn + 1];
                    write_hT(VWT, gm, gn, v0, v1);
                } else {
                    write_h(T, gm, gn, EMB, v0 * tscale, v1 * tscale);
                }
            }
}

// ---- scores: P~ = exp(T x^T + su + sv) (scale folded into T/su/sv) ----
__global__ __launch_bounds__(256, 2)
void scores_gemm(const __half* __restrict__ T, const __half* __restrict__ xb,
                 const float* __restrict__ su, const float* __restrict__ sv,
                 __half* __restrict__ Pb, float* __restrict__ Spart)
{
    extern __shared__ __align__(1024) char smem[];
    const uint32_t smem_base = smem_to_u32(smem);
    const int tid = threadIdx.x;
    const int wid = tid >> 5;
    const int lane = tid & 31;
    const int warp_m = wid & 3;
    const int warp_n = wid >> 2;

    int bid = blockIdx.x;
    int z = bid >> 8;
    int rem = bid & 255;
    int y = rem >> 4;
    int xt = rem & 15;
    int m0 = y * 128;
    int n0 = xt * 128;
    const __half* A = T + (long long)z * SEQ * EMB;
    const __half* B = xb + (long long)z * SEQ * EMB;
    __half* P = Pb + (long long)z * SEQ * SEQ;

    float acc[2][8][4];
    gemm_mainloop(A, B, m0, n0, EMB, smem_base, tid, lane, warp_m, warp_n, acc);

    const int rbase = m0 + warp_m * 32 + (lane >> 2);
    const int cbase = n0 + warp_n * 64 + (lane & 3) * 2;

    float rs[2][2];
    rs[0][0] = rs[0][1] = rs[1][0] = rs[1][1] = 0.0f;

    #pragma unroll
    for (int mi = 0; mi < 2; mi++)
        #pragma unroll
        for (int half = 0; half < 2; half++) {
            int gm = rbase + mi * 16 + half * 8;
            float rowadd = su[(long long)z * SEQ + gm];
            #pragma unroll
            for (int ni = 0; ni < 8; ni++) {
                int gn = cbase + ni * 8;
                float c0 = sv[(long long)z * SEQ + gn];
                float c1 = sv[(long long)z * SEQ + gn + 1];
                float e0 = __expf(acc[mi][ni][half * 2 + 0] + rowadd + c0);
                float e1 = __expf(acc[mi][ni][half * 2 + 1] + rowadd + c1);
                write_h(P, gm, gn, SEQ, e0, e1);
                rs[mi][half] += e0 + e1;
            }
        }

    #pragma unroll
    for (int mi = 0; mi < 2; mi++)
        #pragma unroll
        for (int hf = 0; hf < 2; hf++) {
            float r = rs[mi][hf];
            r += __shfl_xor_sync(0xffffffffu, r, 1);
            r += __shfl_xor_sync(0xffffffffu, r, 2);
            if ((lane & 3) == 0) {
                int gm = rbase + mi * 16 + hf * 8;
                long long rrow = (long long)z * SEQ + gm;
                Spart[rrow * 32 + xt * 2 + warp_n] = r;
            }
        }
}

// ---- final: out = inv[row]*(P~ . VWT) + bo, rowsum inlined ----
__global__ __launch_bounds__(256, 2)
void final_gemm(const __half* __restrict__ Pb, const __half* __restrict__ VWT,
                const float* __restrict__ Spart, const float* __restrict__ bo,
                float* __restrict__ Out)
{
    extern __shared__ __align__(1024) char smem[];
    __shared__ float s_inv[128];
    const uint32_t smem_base = smem_to_u32(smem);
    const int tid = threadIdx.x;
    const int wid = tid >> 5;
    const int lane = tid & 31;
    const int warp_m = wid & 3;
    const int warp_n = wid >> 2;

    const int z = blockIdx.z;
    const __half* A = Pb + (long long)z * SEQ * SEQ;
    const __half* B = VWT + (long long)z * EMB * SEQ;
    float* O = Out + (long long)z * SEQ * EMB;

    const int m0 = blockIdx.y * 128;
    const int n0 = blockIdx.x * 128;

    {
        int r = tid >> 1;
        int sg = (tid & 1) * 4;
        const float4* p = (const float4*)(Spart + ((long long)z * SEQ + m0 + r) * 32);
        float s = 0.0f;
        #pragma unroll
        for (int i = 0; i < 4; i++) {
            float4 f = p[sg + i];
            s += f.x + f.y + f.z + f.w;
        }
        s += __shfl_xor_sync(0xffffffffu, s, 1);
        if ((tid & 1) == 0) s_inv[r] = 1.0f / s;
    }

    float acc[2][8][4];
    gemm_mainloop(A, B, m0, n0, SEQ, smem_base, tid, lane, warp_m, warp_n, acc);

    const int rbase = m0 + warp_m * 32 + (lane >> 2);
    const int cbase = n0 + warp_n * 64 + (lane & 3) * 2;

    #pragma unroll
    for (int mi = 0; mi < 2; mi++)
        #pragma unroll
        for (int ni = 0; ni < 8; ni++)
            #pragma unroll
            for (int half = 0; half < 2; half++) {
                int gm = rbase + mi * 16 + half * 8;
                int gn = cbase + ni * 8;
                float iv = s_inv[gm - m0];
                float v0 = acc[mi][ni][half * 2 + 0] * iv + bo[gn];
                float v1 = acc[mi][ni][half * 2 + 1] * iv + bo[gn + 1];
                *(float2*)&O[(long long)gm * EMB + gn] = make_float2(v0, v1);
            }
}

// ---------------- launch ----------------
extern "C" void kernel_launch(void* const* d_in, const int* in_sizes, int n_in,
                              void* d_out, int out_size)
{
    const float* x  = (const float*)d_in[0];
    const float* Wq = (const float*)d_in[1];
    const float* bq = (const float*)d_in[2];
    const float* Wk = (const float*)d_in[3];
    const float* bk = (const float*)d_in[4];
    const float* Wv = (const float*)d_in[5];
    const float* bv = (const float*)d_in[6];
    const float* Wo = (const float*)d_in[7];
    const float* bo = (const float*)d_in[8];
    float* out = (float*)d_out;

    __half *xb, *WqT, *WkT, *WvT, *Woh, *H, *G, *T, *VWT, *Pb;
    float *wu, *wv, *w2, *cc, *su, *sv, *Spart;
    cudaGetSymbolAddress((void**)&xb,  g_xb);
    cudaGetSymbolAddress((void**)&WqT, g_WqT);
    cudaGetSymbolAddress((void**)&WkT, g_WkT);
    cudaGetSymbolAddress((void**)&WvT, g_WvT);
    cudaGetSymbolAddress((void**)&Woh, g_Wo);
    cudaGetSymbolAddress((void**)&H,   g_H);
    cudaGetSymbolAddress((void**)&G,   g_G);
    cudaGetSymbolAddress((void**)&T,   g_T);
    cudaGetSymbolAddress((void**)&VWT, g_VWT);
    cudaGetSymbolAddress((void**)&Pb,  g_Pb);
    cudaGetSymbolAddress((void**)&wu,  g_wu);
    cudaGetSymbolAddress((void**)&wv,  g_wv);
    cudaGetSymbolAddress((void**)&w2,  g_w2);
    cudaGetSymbolAddress((void**)&cc,  g_c);
    cudaGetSymbolAddress((void**)&su,  g_su);
    cudaGetSymbolAddress((void**)&sv,  g_sv);
    cudaGetSymbolAddress((void**)&Spart, g_Spart);

    cudaFuncSetAttribute(hg_uv,       cudaFuncAttributeMaxDynamicSharedMemorySize, GEMM_SMEM);
    cudaFuncSetAttribute(tvw_gemm,    cudaFuncAttributeMaxDynamicSharedMemorySize, GEMM_SMEM);
    cudaFuncSetAttribute(scores_gemm, cudaFuncAttributeMaxDynamicSharedMemorySize, GEMM_SMEM);
    cudaFuncSetAttribute(final_gemm,  cudaFuncAttributeMaxDynamicSharedMemorySize, GEMM_SMEM);

    prep_kernel<<<PREP_BLOCKS, 256>>>(x, Wq, Wk, Wv, Wo, bq, bk, bv,
                                      xb, WqT, WkT, WvT, Woh, wu, wv, w2, cc);

    hg_uv<<<1152, 256, GEMM_SMEM>>>(WkT, WqT, Woh, WvT, H, G, xb, wu, wv, cc, su, sv);

    tvw_gemm<<<1024, 256, GEMM_SMEM>>>(xb, H, G, w2, T, VWT);

    scores_gemm<<<1024, 256, GEMM_SMEM>>>(T, xb, su, sv, Pb, Spart);

    dim3 gF(EMB / 128, SEQ / 128, BATCH);
    final_gemm<<<gF, 256, GEMM_SMEM>>>(Pb, VWT, Spart, bo, out);
}

// round 17
// speedup vs baseline: 1.0575x; 1.0575x over previous
#include <cuda_runtime.h>
#include <cuda_fp16.h>
#include <cstdint>

#define SEQ   2048
#define EMB   1024
#define BATCH 4
#define MTOT  (BATCH * SEQ)   // 8192

// ---------------- scratch (device globals; allocation-free) ----------------
__device__ __half g_xb [(long long)MTOT * EMB];
__device__ __half g_WqT[(long long)EMB * EMB];
__device__ __half g_WkT[(long long)EMB * EMB];
__device__ __half g_WvT[(long long)EMB * EMB];
__device__ __half g_Wo [(long long)EMB * EMB];
__device__ __half g_H  [(long long)EMB * EMB];          // H = Wk^T·Wq
__device__ __half g_G  [(long long)EMB * EMB];          // G = Wo·Wv
__device__ float  g_wu [EMB];
__device__ float  g_wv [EMB];
__device__ float  g_w2 [EMB];
__device__ float  g_c  [1];
__device__ float  g_su [MTOT];
__device__ float  g_sv [MTOT];
__device__ __half g_T  [(long long)MTOT * EMB];         // T = (x·H^T)/32
__device__ __half g_VWT[(long long)BATCH * EMB * SEQ];
__device__ __half g_Pb [(long long)BATCH * SEQ * SEQ];
__device__ float  g_Spart[(long long)MTOT * 32];

// ---------------- helpers ----------------
__device__ __forceinline__ uint32_t smem_to_u32(const void* p) {
    uint32_t a;
    asm("{ .reg .u64 t; cvta.to.shared.u64 t, %1; cvt.u32.u64 %0, t; }" : "=r"(a) : "l"(p));
    return a;
}

#define CP_ASYNC16(dst, src) \
    asm volatile("cp.async.cg.shared.global [%0], [%1], 16;" :: "r"(dst), "l"(src))
#define CP_COMMIT() asm volatile("cp.async.commit_group;" ::: "memory")

__device__ __forceinline__ void ldmatrix_x4(uint32_t& r0, uint32_t& r1, uint32_t& r2, uint32_t& r3,
                                            uint32_t addr) {
    asm volatile("ldmatrix.sync.aligned.m8n8.x4.shared.b16 {%0,%1,%2,%3}, [%4];"
                 : "=r"(r0), "=r"(r1), "=r"(r2), "=r"(r3) : "r"(addr));
}

__device__ __forceinline__ void mma16816(float* c, uint32_t a0, uint32_t a1, uint32_t a2, uint32_t a3,
                                         uint32_t b0, uint32_t b1) {
    asm volatile("mma.sync.aligned.m16n8k16.row.col.f32.f16.f16.f32 "
                 "{%0,%1,%2,%3}, {%4,%5,%6,%7}, {%8,%9}, {%0,%1,%2,%3};"
                 : "+f"(c[0]), "+f"(c[1]), "+f"(c[2]), "+f"(c[3])
                 : "r"(a0), "r"(a1), "r"(a2), "r"(a3), "r"(b0), "r"(b1));
}

__device__ __forceinline__ uint4 pack8h(const float* v) {
    uint32_t h[4];
    #pragma unroll
    for (int i = 0; i < 4; i++) {
        __half2 hp = __halves2half2(__float2half_rn(v[2 * i]), __float2half_rn(v[2 * i + 1]));
        h[i] = *(uint32_t*)&hp;
    }
    return make_uint4(h[0], h[1], h[2], h[3]);
}

// ---------------- conversions (R15 structure) ----------------
__global__ __launch_bounds__(256)
void cvt_x(const float* __restrict__ in, __half* __restrict__ out)
{
    long long idx = ((long long)blockIdx.x * blockDim.x + threadIdx.x) * 8;
    const float4* src = (const float4*)(in + idx);
    float v[8];
    float4 f0 = src[0], f1 = src[1];
    v[0]=f0.x; v[1]=f0.y; v[2]=f0.z; v[3]=f0.w;
    v[4]=f1.x; v[5]=f1.y; v[6]=f1.z; v[7]=f1.w;
    *(uint4*)(out + idx) = pack8h(v);
}

__global__ void cvt_wt(const float* __restrict__ Wq, const float* __restrict__ Wk,
                       const float* __restrict__ Wv, const float* __restrict__ Wo,
                       __half* __restrict__ WqT, __half* __restrict__ WkT,
                       __half* __restrict__ WvT, __half* __restrict__ Woh)
{
    int w = blockIdx.z;
    const float* src = (w == 0) ? Wq : (w == 1) ? Wk : (w == 2) ? Wv : Wo;
    __half* dst = (w == 0) ? WqT : (w == 1) ? WkT : (w == 2) ? WvT : Woh;
    int r0 = blockIdx.y * 32;
    int c0 = blockIdx.x * 32;
    int tx = threadIdx.x, ty = threadIdx.y;   // 32 x 8

    if (w == 3) {
        #pragma unroll
        for (int k = 0; k < 4; k++) {
            int f = r0 + ty + k * 8;
            dst[(long long)f * EMB + c0 + tx] = __float2half_rn(src[(long long)f * EMB + c0 + tx]);
        }
        return;
    }
    __shared__ __half sm[32][36];
    #pragma unroll
    for (int k = 0; k < 4; k++) {
        int f = r0 + ty + k * 8;
        sm[tx][ty + k * 8] = __float2half_rn(src[(long long)f * EMB + c0 + tx]);
    }
    __syncthreads();
    #pragma unroll
    for (int k = 0; k < 4; k++) {
        int e = c0 + ty + k * 8;
        dst[(long long)e * EMB + r0 + tx] = sm[ty + k * 8][tx];
    }
}

__global__ __launch_bounds__(256)
void vec_kernel(const float* __restrict__ Wq, const float* __restrict__ Wk,
                const float* __restrict__ Wo,
                const float* __restrict__ bq, const float* __restrict__ bk,
                const float* __restrict__ bv,
                float* __restrict__ wu, float* __restrict__ wv,
                float* __restrict__ w2, float* __restrict__ cc)
{
    int y = blockIdx.y;
    int tid = threadIdx.x;
    if (y == 0 || y == 1) {
        int e = blockIdx.x * 256 + tid;
        if (e >= EMB) return;
        const float* W = (y == 0) ? Wq : Wk;
        const float* b = (y == 0) ? bk : bq;
        float* o = (y == 0) ? wu : wv;
        float s = 0.0f;
        for (int f = 0; f < EMB; f++)
            s += W[(long long)f * EMB + e] * b[f];
        o[e] = s;
    } else if (y == 2) {
        if (blockIdx.x != 0) return;
        __shared__ float red[256];
        float s = 0.0f;
        for (int f = tid; f < EMB; f += 256) s += bq[f] * bk[f];
        red[tid] = s;
        __syncthreads();
        for (int o = 128; o > 0; o >>= 1) {
            if (tid < o) red[tid] += red[tid + o];
            __syncthreads();
        }
        if (tid == 0) cc[0] = red[0];
    } else {
        int f = blockIdx.x * 32 + (tid >> 3);
        int seg = tid & 7;
        const float* row = Wo + (long long)f * EMB + seg * 128;
        float s = 0.0f;
        #pragma unroll
        for (int g = 0; g < 128; g++) s += row[g] * bv[seg * 128 + g];
        s += __shfl_xor_sync(0xffffffffu, s, 1);
        s += __shfl_xor_sync(0xffffffffu, s, 2);
        s += __shfl_xor_sync(0xffffffffu, s, 4);
        if (seg == 0) w2[f] = s;
    }
}

// ---------------- epilogue writers ----------------
__device__ __forceinline__ void write_h(__half* O, int gm, int gn, int Nl,
                                        float v0, float v1) {
    __half2 hp = __halves2half2(__float2half_rn(v0), __float2half_rn(v1));
    *(__half2*)&O[(long long)gm * Nl + gn] = hp;
}
__device__ __forceinline__ void write_hT(__half* O, int gm, int gn,
                                         float v0, float v1) {
    int b = gm >> 11;
    int sdx = gm & (SEQ - 1);
    long long base = (long long)b * EMB * SEQ + (long long)gn * SEQ + sdx;
    O[base] = __float2half_rn(v0);
    O[base + SEQ] = __float2half_rn(v1);
}

// ---------------- HMMA mainloop (proven core) ----------------
#define BK      64
#define NSTAGE  3
#define STAGE_BYTES 32768
#define GEMM_SMEM (NSTAGE * STAGE_BYTES)

__device__ __forceinline__ void gemm_mainloop(
    const __half* __restrict__ A, const __half* __restrict__ B,
    int m0, int n0, int Ktot, uint32_t smem_base, int tid, int lane,
    int warp_m, int warp_n, float (&acc)[2][8][4])
{
    const int nchunks = Ktot / BK;

    auto load_stage = [&](int chunk, int s) {
        uint32_t sa = smem_base + s * STAGE_BYTES;
        uint32_t sb = sa + 16384;
        long long k0 = (long long)chunk * BK;
        #pragma unroll
        for (int t = 0; t < 4; t++) {
            int idx = tid + t * 256;
            int r = idx >> 3, c = idx & 7;
            uint32_t off = (uint32_t)((r * 8 + (c ^ (r & 7))) * 16);
            CP_ASYNC16(sa + off, (const void*)(A + (long long)(m0 + r) * Ktot + k0 + c * 8));
            CP_ASYNC16(sb + off, (const void*)(B + (long long)(n0 + r) * Ktot + k0 + c * 8));
        }
        CP_COMMIT();
    };

    #pragma unroll
    for (int mi = 0; mi < 2; mi++)
        #pragma unroll
        for (int ni = 0; ni < 8; ni++)
            #pragma unroll
            for (int r = 0; r < 4; r++)
                acc[mi][ni][r] = 0.0f;

    load_stage(0, 0);
    load_stage(1, 1);

    const int a_row = (lane & 15);
    const int a_half = lane >> 4;
    const int b_noff = (lane & 7) + ((lane & 16) ? 8 : 0);
    const int b_kg = (lane & 8) ? 1 : 0;

    for (int i = 0; i < nchunks; i++) {
        if (i + 1 < nchunks) {
            asm volatile("cp.async.wait_group 1;" ::: "memory");
        } else {
            asm volatile("cp.async.wait_group 0;" ::: "memory");
        }
        __syncthreads();

        if (i + 2 < nchunks) load_stage(i + 2, (i + 2) % NSTAGE);

        const int s = i % NSTAGE;
        const uint32_t sa = smem_base + s * STAGE_BYTES;
        const uint32_t sb = sa + 16384;

        #pragma unroll
        for (int kk = 0; kk < 4; kk++) {
            uint32_t af[2][4];
            #pragma unroll
            for (int mi = 0; mi < 2; mi++) {
                int row = warp_m * 32 + mi * 16 + a_row;
                int g = (kk * 2 + a_half) ^ (row & 7);
                ldmatrix_x4(af[mi][0], af[mi][1], af[mi][2], af[mi][3],
                            sa + (uint32_t)((row * 8 + g) * 16));
            }
            uint32_t bf[4][4];
            #pragma unroll
            for (int nt = 0; nt < 4; nt++) {
                int row = warp_n * 64 + nt * 16 + b_noff;
                int g = (kk * 2 + b_kg) ^ (row & 7);
                ldmatrix_x4(bf[nt][0], bf[nt][1], bf[nt][2], bf[nt][3],
                            sb + (uint32_t)((row * 8 + g) * 16));
            }
            #pragma unroll
            for (int mi = 0; mi < 2; mi++)
                #pragma unroll
                for (int ni = 0; ni < 8; ni++) {
                    int nt = ni >> 1;
                    uint32_t bb0 = (ni & 1) ? bf[nt][2] : bf[nt][0];
                    uint32_t bb1 = (ni & 1) ? bf[nt][3] : bf[nt][1];
                    mma16816(acc[mi][ni], af[mi][0], af[mi][1], af[mi][2], af[mi][3], bb0, bb1);
                }
        }
    }
}

// ---- H = Wk^T·Wq (64 tiles), G = Wo·Wv (64 tiles) ----
__global__ __launch_bounds__(256, 2)
void hg_gemm(const __half* __restrict__ WkT, const __half* __restrict__ WqT,
             const __half* __restrict__ Wo, const __half* __restrict__ WvT,
             __half* __restrict__ H, __half* __restrict__ G)
{
    extern __shared__ __align__(1024) char smem[];
    const uint32_t smem_base = smem_to_u32(smem);
    const int tid = threadIdx.x;
    const int wid = tid >> 5;
    const int lane = tid & 31;
    const int warp_m = wid & 3;
    const int warp_n = wid >> 2;

    int bid = blockIdx.x;
    bool isG = (bid >= 64);
    int t = isG ? bid - 64 : bid;
    int m0 = (t >> 3) * 128;
    int n0 = (t & 7) * 128;
    const __half* A = isG ? Wo : WkT;
    const __half* B = isG ? WvT : WqT;
    __half* O = isG ? G : H;

    float acc[2][8][4];
    gemm_mainloop(A, B, m0, n0, EMB, smem_base, tid, lane, warp_m, warp_n, acc);

    const int rbase = m0 + warp_m * 32 + (lane >> 2);
    const int cbase = n0 + warp_n * 64 + (lane & 3) * 2;
    #pragma unroll
    for (int mi = 0; mi < 2; mi++)
        #pragma unroll
        for (int ni = 0; ni < 8; ni++)
            #pragma unroll
            for (int half = 0; half < 2; half++) {
                int gm = rbase + mi * 16 + half * 8;
                int gn = cbase + ni * 8;
                write_h(O, gm, gn, EMB, acc[mi][ni][half * 2 + 0], acc[mi][ni][half * 2 + 1]);
            }
}

// ---- tvw + uv: bid<512 T tiles, bid<1024 VW tiles, bid>=1024 uv blocks (64 rows) ----
__global__ __launch_bounds__(256, 2)
void tvw_uv(const __half* __restrict__ xb, const __half* __restrict__ H,
            const __half* __restrict__ G, const float* __restrict__ w2,
            __half* __restrict__ T, __half* __restrict__ VWT,
            const float* __restrict__ wu, const float* __restrict__ wv,
            const float* __restrict__ cc,
            float* __restrict__ su, float* __restrict__ sv)
{
    const int tid = threadIdx.x;
    int bid = blockIdx.x;

    if (bid >= 1024) {
        // uv: 128 blocks x 64 rows; warp per row, 8 iterations
        const float scale = 1.0f / 32.0f;
        int wid = tid >> 5;
        int lane = tid & 31;
        long long row0 = (long long)(bid - 1024) * 64 + wid;
        #pragma unroll
        for (int it = 0; it < 8; it++) {
            long long row = row0 + it * 8;
            const uint4* xr = (const uint4*)(xb + row * EMB);
            float du = 0.0f, dv = 0.0f;
            #pragma unroll
            for (int j = 0; j < 4; j++) {
                int u = j * 32 + lane;
                uint4 q = xr[u];
                const __half2* hp = (const __half2*)&q;
                int e0 = u * 8;
                float4 a0 = *(const float4*)(wu + e0);
                float4 a1 = *(const float4*)(wu + e0 + 4);
                float4 b0 = *(const float4*)(wv + e0);
                float4 b1 = *(const float4*)(wv + e0 + 4);
                float2 x0 = __half22float2(hp[0]);
                float2 x1 = __half22float2(hp[1]);
                float2 x2 = __half22float2(hp[2]);
                float2 x3 = __half22float2(hp[3]);
                du += x0.x*a0.x + x0.y*a0.y + x1.x*a0.z + x1.y*a0.w
                    + x2.x*a1.x + x2.y*a1.y + x3.x*a1.z + x3.y*a1.w;
                dv += x0.x*b0.x + x0.y*b0.y + x1.x*b0.z + x1.y*b0.w
                    + x2.x*b1.x + x2.y*b1.y + x3.x*b1.z + x3.y*b1.w;
            }
            #pragma unroll
            for (int o = 16; o > 0; o >>= 1) {
                du += __shfl_xor_sync(0xffffffffu, du, o);
                dv += __shfl_xor_sync(0xffffffffu, dv, o);
            }
            if (lane == 0) {
                su[row] = scale * (du + cc[0]);
                sv[row] = scale * dv;
            }
        }
        return;
    }

    extern __shared__ __align__(1024) char smem[];
    const uint32_t smem_base = smem_to_u32(smem);
    const int wid = tid >> 5;
    const int lane = tid & 31;
    const int warp_m = wid & 3;
    const int warp_n = wid >> 2;

    bool isVW = (bid >= 512);
    int t = isVW ? bid - 512 : bid;
    int m0 = (t >> 3) * 128;
    int n0 = (t & 7) * 128;
    const __half* B = isVW ? G : H;

    float acc[2][8][4];
    gemm_mainloop(xb, B, m0, n0, EMB, smem_base, tid, lane, warp_m, warp_n, acc);

    const float tscale = 1.0f / 32.0f;
    const int rbase = m0 + warp_m * 32 + (lane >> 2);
    const int cbase = n0 + warp_n * 64 + (lane & 3) * 2;
    #pragma unroll
    for (int mi = 0; mi < 2; mi++)
        #pragma unroll
        for (int ni = 0; ni < 8; ni++)
            #pragma unroll
            for (int half = 0; half < 2; half++) {
                int gm = rbase + mi * 16 + half * 8;
                int gn = cbase + ni * 8;
                float v0 = acc[mi][ni][half * 2 + 0];
                float v1 = acc[mi][ni][half * 2 + 1];
                if (isVW) {
                    v0 += w2[gn]; v1 += w2[gn + 1];
                    write_hT(VWT, gm, gn, v0, v1);
                } else {
                    write_h(T, gm, gn, EMB, v0 * tscale, v1 * tscale);
                }
            }
}

// ---- scores: P~ = exp(T x^T + su + sv) (scale pre-folded) ----
__global__ __launch_bounds__(256, 2)
void scores_gemm(const __half* __restrict__ T, const __half* __restrict__ xb,
                 const float* __restrict__ su, const float* __restrict__ sv,
                 __half* __restrict__ Pb, float* __restrict__ Spart)
{
    extern __shared__ __align__(1024) char smem[];
    const uint32_t smem_base = smem_to_u32(smem);
    const int tid = threadIdx.x;
    const int wid = tid >> 5;
    const int lane = tid & 31;
    const int warp_m = wid & 3;
    const int warp_n = wid >> 2;

    int bid = blockIdx.x;
    int z = bid >> 8;
    int rem = bid & 255;
    int y = rem >> 4;
    int xt = rem & 15;
    int m0 = y * 128;
    int n0 = xt * 128;
    const __half* A = T + (long long)z * SEQ * EMB;
    const __half* B = xb + (long long)z * SEQ * EMB;
    __half* P = Pb + (long long)z * SEQ * SEQ;

    float acc[2][8][4];
    gemm_mainloop(A, B, m0, n0, EMB, smem_base, tid, lane, warp_m, warp_n, acc);

    const int rbase = m0 + warp_m * 32 + (lane >> 2);
    const int cbase = n0 + warp_n * 64 + (lane & 3) * 2;

    float rs[2][2];
    rs[0][0] = rs[0][1] = rs[1][0] = rs[1][1] = 0.0f;

    #pragma unroll
    for (int mi = 0; mi < 2; mi++)
        #pragma unroll
        for (int half = 0; half < 2; half++) {
            int gm = rbase + mi * 16 + half * 8;
            float rowadd = su[(long long)z * SEQ + gm];
            #pragma unroll
            for (int ni = 0; ni < 8; ni++) {
                int gn = cbase + ni * 8;
                float c0 = sv[(long long)z * SEQ + gn];
                float c1 = sv[(long long)z * SEQ + gn + 1];
                float e0 = __expf(acc[mi][ni][half * 2 + 0] + rowadd + c0);
                float e1 = __expf(acc[mi][ni][half * 2 + 1] + rowadd + c1);
                write_h(P, gm, gn, SEQ, e0, e1);
                rs[mi][half] += e0 + e1;
            }
        }

    #pragma unroll
    for (int mi = 0; mi < 2; mi++)
        #pragma unroll
        for (int hf = 0; hf < 2; hf++) {
            float r = rs[mi][hf];
            r += __shfl_xor_sync(0xffffffffu, r, 1);
            r += __shfl_xor_sync(0xffffffffu, r, 2);
            if ((lane & 3) == 0) {
                int gm = rbase + mi * 16 + hf * 8;
                long long rrow = (long long)z * SEQ + gm;
                Spart[rrow * 32 + xt * 2 + warp_n] = r;
            }
        }
}

// ---- final: out = inv[row]*(P~ . VWT) + bo, rowsum inlined ----
__global__ __launch_bounds__(256, 2)
void final_gemm(const __half* __restrict__ Pb, const __half* __restrict__ VWT,
                const float* __restrict__ Spart, const float* __restrict__ bo,
                float* __restrict__ Out)
{
    extern __shared__ __align__(1024) char smem[];
    __shared__ float s_inv[128];
    const uint32_t smem_base = smem_to_u32(smem);
    const int tid = threadIdx.x;
    const int wid = tid >> 5;
    const int lane = tid & 31;
    const int warp_m = wid & 3;
    const int warp_n = wid >> 2;

    const int z = blockIdx.z;
    const __half* A = Pb + (long long)z * SEQ * SEQ;
    const __half* B = VWT + (long long)z * EMB * SEQ;
    float* O = Out + (long long)z * SEQ * EMB;

    const int m0 = blockIdx.y * 128;
    const int n0 = blockIdx.x * 128;

    {
        int r = tid >> 1;
        int sg = (tid & 1) * 4;
        const float4* p = (const float4*)(Spart + ((long long)z * SEQ + m0 + r) * 32);
        float s = 0.0f;
        #pragma unroll
        for (int i = 0; i < 4; i++) {
            float4 f = p[sg + i];
            s += f.x + f.y + f.z + f.w;
        }
        s += __shfl_xor_sync(0xffffffffu, s, 1);
        if ((tid & 1) == 0) s_inv[r] = 1.0f / s;
    }

    float acc[2][8][4];
    gemm_mainloop(A, B, m0, n0, SEQ, smem_base, tid, lane, warp_m, warp_n, acc);

    const int rbase = m0 + warp_m * 32 + (lane >> 2);
    const int cbase = n0 + warp_n * 64 + (lane & 3) * 2;

    #pragma unroll
    for (int mi = 0; mi < 2; mi++)
        #pragma unroll
        for (int ni = 0; ni < 8; ni++)
            #pragma unroll
            for (int half = 0; half < 2; half++) {
                int gm = rbase + mi * 16 + half * 8;
                int gn = cbase + ni * 8;
                float iv = s_inv[gm - m0];
                float v0 = acc[mi][ni][half * 2 + 0] * iv + bo[gn];
                float v1 = acc[mi][ni][half * 2 + 1] * iv + bo[gn + 1];
                *(float2*)&O[(long long)gm * EMB + gn] = make_float2(v0, v1);
            }
}

// ---------------- launch ----------------
extern "C" void kernel_launch(void* const* d_in, const int* in_sizes, int n_in,
                              void* d_out, int out_size)
{
    const float* x  = (const float*)d_in[0];
    const float* Wq = (const float*)d_in[1];
    const float* bq = (const float*)d_in[2];
    const float* Wk = (const float*)d_in[3];
    const float* bk = (const float*)d_in[4];
    const float* Wv = (const float*)d_in[5];
    const float* bv = (const float*)d_in[6];
    const float* Wo = (const float*)d_in[7];
    const float* bo = (const float*)d_in[8];
    float* out = (float*)d_out;

    __half *xb, *WqT, *WkT, *WvT, *Woh, *H, *G, *T, *VWT, *Pb;
    float *wu, *wv, *w2, *cc, *su, *sv, *Spart;
    cudaGetSymbolAddress((void**)&xb,  g_xb);
    cudaGetSymbolAddress((void**)&WqT, g_WqT);
    cudaGetSymbolAddress((void**)&WkT, g_WkT);
    cudaGetSymbolAddress((void**)&WvT, g_WvT);
    cudaGetSymbolAddress((void**)&Woh, g_Wo);
    cudaGetSymbolAddress((void**)&H,   g_H);
    cudaGetSymbolAddress((void**)&G,   g_G);
    cudaGetSymbolAddress((void**)&T,   g_T);
    cudaGetSymbolAddress((void**)&VWT, g_VWT);
    cudaGetSymbolAddress((void**)&Pb,  g_Pb);
    cudaGetSymbolAddress((void**)&wu,  g_wu);
    cudaGetSymbolAddress((void**)&wv,  g_wv);
    cudaGetSymbolAddress((void**)&w2,  g_w2);
    cudaGetSymbolAddress((void**)&cc,  g_c);
    cudaGetSymbolAddress((void**)&su,  g_su);
    cudaGetSymbolAddress((void**)&sv,  g_sv);
    cudaGetSymbolAddress((void**)&Spart, g_Spart);

    cudaFuncSetAttribute(hg_gemm,     cudaFuncAttributeMaxDynamicSharedMemorySize, GEMM_SMEM);
    cudaFuncSetAttribute(tvw_uv,      cudaFuncAttributeMaxDynamicSharedMemorySize, GEMM_SMEM);
    cudaFuncSetAttribute(scores_gemm, cudaFuncAttributeMaxDynamicSharedMemorySize, GEMM_SMEM);
    cudaFuncSetAttribute(final_gemm,  cudaFuncAttributeMaxDynamicSharedMemorySize, GEMM_SMEM);

    // 1) conversions + tiny precomputes (R15 structure)
    cvt_x<<<(unsigned)(((long long)MTOT * EMB / 8) / 256), 256>>>(x, xb);
    {
        dim3 g(32, 32, 4), b(32, 8);
        cvt_wt<<<g, b>>>(Wq, Wk, Wv, Wo, WqT, WkT, WvT, Woh);
    }
    {
        dim3 g(32, 4);
        vec_kernel<<<g, 256>>>(Wq, Wk, Wo, bq, bk, bv, wu, wv, w2, cc);
    }

    // 2) H, G
    hg_gemm<<<128, 256, GEMM_SMEM>>>(WkT, WqT, Woh, WvT, H, G);

    // 3) T + VW^T GEMMs (1024) + uv GEMV (128)
    tvw_uv<<<1152, 256, GEMM_SMEM>>>(xb, H, G, w2, T, VWT, wu, wv, cc, su, sv);

    // 4) scores + exp + partial sums
    scores_gemm<<<1024, 256, GEMM_SMEM>>>(T, xb, su, sv, Pb, Spart);

    // 5) final (rowsum inlined)
    dim3 gF(EMB / 128, SEQ / 128, BATCH);
    final_gemm<<<gF, 256, GEMM_SMEM>>>(Pb, VWT, Spart, bo, out);
}